// round 9
// baseline (speedup 1.0000x reference)
#include <cuda_runtime.h>

#define NLAY 5
#define MIX  5
#define MF   50

typedef unsigned long long u64;

__device__ double g_p1[1024];
__device__ double g_p2[1024];
__device__ unsigned int g_cnt = 0;

// ---- f32x2 packed helpers ----
__device__ __forceinline__ u64 PK(float lo, float hi) {
    u64 r; asm("mov.b64 %0,{%1,%2};" : "=l"(r) : "f"(lo), "f"(hi)); return r;
}
__device__ __forceinline__ void UPK(u64 v, float& lo, float& hi) {
    asm("mov.b64 {%0,%1},%2;" : "=f"(lo), "=f"(hi) : "l"(v));
}
__device__ __forceinline__ u64 SP(float x) { return PK(x, x); }
__device__ __forceinline__ u64 F2(u64 a, u64 b, u64 c) {
    u64 r; asm("fma.rn.f32x2 %0,%1,%2,%3;" : "=l"(r) : "l"(a), "l"(b), "l"(c)); return r;
}
__device__ __forceinline__ u64 M2(u64 a, u64 b) {
    u64 r; asm("mul.rn.f32x2 %0,%1,%2;" : "=l"(r) : "l"(a), "l"(b)); return r;
}
__device__ __forceinline__ u64 A2(u64 a, u64 b) {
    u64 r; asm("add.rn.f32x2 %0,%1,%2;" : "=l"(r) : "l"(a), "l"(b)); return r;
}

__device__ __forceinline__ float ex2_(float v) {
    float r; asm("ex2.approx.f32 %0,%1;" : "=f"(r) : "f"(v)); return r;
}
__device__ __forceinline__ float sigmoidf_(float v) {
    return __fdividef(1.f, 1.f + __expf(-v));
}
__device__ __forceinline__ float softplusf_(float v) {
    return fmaxf(v, 0.f) + __logf(1.f + __expf(-fabsf(v)));
}
// Abramowitz-Stegun 26.2.17 normal CDF, |abs err| < 7.5e-8
__device__ __forceinline__ float ndtr_(float x) {
    float ax = fabsf(x);
    float t = __fdividef(1.f, fmaf(0.2316419f, ax, 1.f));
    float poly = t * fmaf(t, fmaf(t, fmaf(t, fmaf(t, 1.330274429f, -1.821255978f),
                         1.781477937f), -0.356563782f), 0.319381530f);
    float c = 0.39894228040f * __expf(-0.5f * ax * ax) * poly;
    return (x >= 0.f) ? 1.f - c : c;
}
// Giles erfinv-based inverse normal CDF: ndtri(p) = sqrt(2)*erfinv(2p-1)
__device__ __forceinline__ float ndtri_(float p) {
    float x = fmaf(2.f, p, -1.f);
    x = fminf(fmaxf(x, -0.9999990f), 0.9999990f);
    float w = -__logf(fmaf(-x, x, 1.f));
    float z;
    if (w < 5.f) {
        w -= 2.5f;
        z =            2.81022636e-08f;
        z = fmaf(z, w, 3.43273939e-07f);
        z = fmaf(z, w, -3.5233877e-06f);
        z = fmaf(z, w, -4.39150654e-06f);
        z = fmaf(z, w, 0.00021858087f);
        z = fmaf(z, w, -0.00125372503f);
        z = fmaf(z, w, -0.00417768164f);
        z = fmaf(z, w, 0.246640727f);
        z = fmaf(z, w, 1.50140941f);
    } else {
        w = __fsqrt_rn(w) - 3.f;
        z =            -0.000200214257f;
        z = fmaf(z, w, 0.000100950558f);
        z = fmaf(z, w, 0.00134934322f);
        z = fmaf(z, w, -0.00367342844f);
        z = fmaf(z, w, 0.00573950773f);
        z = fmaf(z, w, -0.0076224613f);
        z = fmaf(z, w, 0.00943887047f);
        z = fmaf(z, w, 1.00167406f);
        z = fmaf(z, w, 2.83297682f);
    }
    return 1.41421356237f * z * x;
}

__global__ __launch_bounds__(128) void bnn_all(
    const float* __restrict__ x, const float* __restrict__ s,
    const float* __restrict__ ucat, const float* __restrict__ utr,
    float* __restrict__ out, int B)
{
    __shared__ float s_cf[MF], s_nlm[MF];
    if (threadIdx.x < MF) {
        int i = threadIdx.x;
        s_cf[i]  = 1.9869176531e-4f * exp2f(0.16948612698f * (float)i);
        s_nlm[i] = 7.4035748111f - 0.1020408163f * (float)i;
    }
    __syncthreads();

    int b = blockIdx.x * blockDim.x + threadIdx.x;
    float ll_sum = 0.f;
    float lq = 0.f;
    if (b < B) {
        const float* sb = s + (size_t)b * 55;
        const float* xb = x + (size_t)b * 105;

        // ---- mixture weights ----
        float sq[MIX]; float sumsq = 0.f;
        #pragma unroll
        for (int m = 0; m < MIX; m++) { float v = sb[m*11 + 10]; sq[m] = v*v; sumsq += sq[m]; }
        float rinv = __fdividef(1.f, sumsq);

        // ---- categorical selection ----
        float u = ucat[b];
        float cum = 0.f; int cnt = 0;
        #pragma unroll
        for (int m = 0; m < MIX; m++) { cum += sq[m] * rinv; cnt += (u > cum) ? 1 : 0; }
        int comp = min(cnt, MIX - 1);

        // ---- truncated-normal sampling ----
        float q[NLAY];
        const float* sc = sb + comp * 11;
        #pragma unroll
        for (int l = 0; l < NLAY; l++) {
            float lc = 4.f * sigmoidf_(sc[l]);
            float sg = softplusf_(sc[5 + l]);
            float rs = __fdividef(1.f, sg);
            float aa = (0.1f - lc) * rs;
            float bb = (3.9f - lc) * rs;
            float Fa = ndtr_(aa);
            float Fb = ndtr_(bb);
            float p  = Fa + utr[(size_t)b * NLAY + l] * (Fb - Fa);
            p = fminf(fmaxf(p, 0.f), 1.f);
            float z = ndtri_(p);
            q[l] = fminf(fmaxf(fmaf(sg, z, lc), 0.1f), 3.9f);
        }

        // ---- physics precompute: packed (hoisted out of freq loop) ----
        float sr[NLAY];
        u64 srP[NLAY], tqP[NLAY - 1];
        #pragma unroll
        for (int l = 0; l < NLAY; l++) {
            sr[l] = ex2_(q[l] * 1.66096404744368f);
            srP[l] = SP(sr[l]);
        }
        #pragma unroll
        for (int j = 0; j < NLAY - 1; j++)
            tqP[j] = SP(2.f * xb[j] * __fdividef(1.f, sr[j]));

        // ---- packed constants ----
        const u64 C130 = SP(0.033333335f), Cm16 = SP(-0.16666667f);
        const u64 C13  = SP(0.33333334f),  Cm13 = SP(-0.33333334f);
        const u64 ONE2 = SP(1.0f), Cm1 = SP(-1.0f);
        const u64 A1  = SP(0.9999993329f),  A3  = SP(-0.3332985605f);
        const u64 A5  = SP(0.1994653599f),  A7  = SP(-0.1390853351f);
        const u64 A9  = SP(0.0964200441f),  A11 = SP(-0.0559098861f);
        const u64 A13 = SP(0.0218612288f),  A15 = SP(-0.0040540580f);
        const u64 C555 = SP(-555.555556f), CLN2 = SP(-0.69314718f);
        const u64 CC = SP(2.58761937f), CL102 = SP(0.30102999566f);
        const u64 PI4 = SP(0.78539816340f);

        u64 acc2 = 0ull;

        // ---- frequency loop: 2 freqs/iter, (1+i)-factored recursion ----
        #pragma unroll 1
        for (int p = 0; p < MF; p += 2) {
            u64 cf2 = PK(s_cf[p], s_cf[p + 1]);
            u64 N0 = M2(cf2, srP[NLAY - 1]);      // Ntil_bottom (real)

            u64 NRv, NCv, DRv, DCv;
            {   // peeled layer j=3 (D=1, Ntil real)
                u64 wj = M2(cf2, srP[3]);
                u64 tt = M2(cf2, tqP[3]);
                u64 t2 = M2(tt, tt);
                u64 pr = F2(tt, C130, Cm16);  pr = F2(pr, tt, C13);
                u64 t3 = M2(tt, t2);
                u64 omt = F2(tt, Cm1, ONE2);
                u64 ejR = F2(pr, t3, omt);
                u64 pc = F2(t2, C130, Cm13);  pc = F2(pc, tt, ONE2);
                u64 nt = M2(tt, Cm1);
                u64 ejC = F2(pc, t2, nt);
                u64 PR = A2(wj, N0);
                u64 MR = F2(N0, Cm1, wj);
                u64 eMR = M2(ejR, MR);
                u64 eMC = M2(ejC, MR);
                NRv = M2(wj, F2(eMR, Cm1, PR));
                NCv = M2(wj, M2(eMC, Cm1));
                DRv = A2(PR, eMR);
                DCv = eMC;
            }
            #pragma unroll
            for (int j = 2; j >= 0; j--) {
                u64 wj = M2(cf2, srP[j]);
                u64 tt = M2(cf2, tqP[j]);
                u64 t2 = M2(tt, tt);
                u64 pr = F2(tt, C130, Cm16);  pr = F2(pr, tt, C13);
                u64 t3 = M2(tt, t2);
                u64 omt = F2(tt, Cm1, ONE2);
                u64 ejR = F2(pr, t3, omt);
                u64 pc = F2(t2, C130, Cm13);  pc = F2(pc, tt, ONE2);
                u64 nt = M2(tt, Cm1);
                u64 ejC = F2(pc, t2, nt);
                u64 wdr = M2(wj, DRv), wdc = M2(wj, DCv);
                u64 PR = A2(wdr, NRv), PC = A2(wdc, NCv);
                u64 MR = F2(NRv, Cm1, wdr), MC = F2(NCv, Cm1, wdc);
                u64 nEjC = M2(ejC, Cm1);
                u64 eMR = F2(nEjC, MC, M2(ejR, MR));
                u64 eMC = F2(ejC, MR, M2(ejR, MC));
                NRv = M2(wj, F2(eMR, Cm1, PR));
                NCv = M2(wj, F2(eMC, Cm1, PC));
                DRv = A2(PR, eMR);
                DCv = A2(PC, eMC);
            }
            u64 n2v = F2(NRv, NRv, M2(NCv, NCv));
            u64 d2v = F2(DRv, DRv, M2(DCv, DCv));
            u64 nrv = F2(NRv, DRv, M2(NCv, DCv));            // Re Ntil*conj(D)
            u64 ncv = F2(NCv, DRv, M2(M2(NRv, DCv), Cm1));   // Im Ntil*conj(D)
            float n2a, n2b, d2a, d2b, ra_, rb_, ca_, cb_;
            UPK(n2v, n2a, n2b); UPK(d2v, d2a, d2b);
            UPK(nrv, ra_, rb_); UPK(ncv, ca_, cb_);

            // aRes = 0.30103*(log2 n2 - log2 d2) + (0.30103 - lmw)
            u64 lgv = PK(__log2f(n2a) - __log2f(d2a), __log2f(n2b) - __log2f(d2b));
            u64 aResV = F2(CL102, lgv, PK(s_nlm[p], s_nlm[p + 1]));
            float aA, aB; UPK(aResV, aA, aB);

            // phase = pi/4 + atan(nc/nr), |nc/nr| < 1 guaranteed
            float r0 = __fdividef(ca_, ra_);
            float r1 = __fdividef(cb_, rb_);
            u64 rv = PK(r0, r1);
            u64 sv = M2(rv, rv);
            u64 pp = F2(sv, A15, A13); pp = F2(pp, sv, A11);
            pp = F2(pp, sv, A9);       pp = F2(pp, sv, A7);
            pp = F2(pp, sv, A5);       pp = F2(pp, sv, A3);
            pp = F2(pp, sv, A1);
            u64 phv = F2(pp, rv, PI4);
            float ph0, ph1; UPK(phv, ph0, ph1);

            float ra0 = __fdividef(aA - xb[NLAY + p],     aA);
            float ra1 = __fdividef(aB - xb[NLAY + p + 1], aB);
            u64 rAv = PK(ra0, ra1);
            u64 lgA = PK(__log2f(fabsf(aA)), __log2f(fabsf(aB)));
            acc2 = A2(acc2, F2(C555, M2(rAv, rAv), F2(CLN2, lgA, CC)));

            float rp0 = __fdividef(ph0 - xb[NLAY + MF + p],     ph0);
            float rp1 = __fdividef(ph1 - xb[NLAY + MF + p + 1], ph1);
            u64 rPv = PK(rp0, rp1);
            u64 lgP = PK(__log2f(ph0), __log2f(ph1));
            acc2 = A2(acc2, F2(C555, M2(rPv, rPv), F2(CLN2, lgP, CC)));
        }
        { float la, lb_; UPK(acc2, la, lb_); ll_sum = la + lb_; }

        // ---- term_q: fused-log form. log pro - SUM(log sg + log dF)
        //      = log( pro / (prod sg * prod dF) )  -> 1 div + 1 log per comp
        float clp[MIX];
        #pragma unroll
        for (int m = 0; m < MIX; m++) {
            const float* sm = sb + m * 11;
            float zacc = 0.f;
            float prod = 1.f;
            #pragma unroll
            for (int l = 0; l < NLAY; l++) {
                float lc = 4.f * sigmoidf_(sm[l]);
                float sg = softplusf_(sm[5 + l]);
                float rs = __fdividef(1.f, sg);
                float a_ = (0.f - lc) * rs;
                float b_ = (4.f - lc) * rs;
                float dF = ndtr_(b_) - ndtr_(a_);
                float zc = (q[l] - lc) * rs;
                zacc = fmaf(-0.5f, zc * zc, zacc);
                prod *= sg * dF;
            }
            // -5 * 0.5 * log(2pi) = -4.59469266
            clp[m] = zacc - 4.59469266f + __logf(__fdividef(sq[m] * rinv, prod));
        }
        float mx = clp[0];
        #pragma unroll
        for (int m = 1; m < MIX; m++) mx = fmaxf(mx, clp[m]);
        float se = 0.f;
        #pragma unroll
        for (int m = 0; m < MIX; m++) se += __expf(clp[m] - mx);
        lq = mx + __logf(se);
    }

    // ---- block reduction (double), 128 threads = 4 warps ----
    double v1 = (double)ll_sum, v2 = (double)lq;
    #pragma unroll
    for (int o = 16; o > 0; o >>= 1) {
        v1 += __shfl_down_sync(0xffffffffu, v1, o);
        v2 += __shfl_down_sync(0xffffffffu, v2, o);
    }
    __shared__ double sh1[4], sh2[4];
    __shared__ bool amLast;
    int lane = threadIdx.x & 31, wid = threadIdx.x >> 5;
    if (lane == 0) { sh1[wid] = v1; sh2[wid] = v2; }
    __syncthreads();
    if (wid == 0) {
        double a = (lane < 4) ? sh1[lane] : 0.0;
        double c = (lane < 4) ? sh2[lane] : 0.0;
        #pragma unroll
        for (int o = 2; o > 0; o >>= 1) {
            a += __shfl_down_sync(0xffffffffu, a, o);
            c += __shfl_down_sync(0xffffffffu, c, o);
        }
        if (lane == 0) {
            g_p1[blockIdx.x] = a;
            g_p2[blockIdx.x] = c;
            __threadfence();
            unsigned int t = atomicAdd(&g_cnt, 1u);
            amLast = (t == gridDim.x - 1);
        }
    }
    __syncthreads();

    if (amLast) {
        __threadfence();
        double s1 = 0.0, s2 = 0.0;
        for (int i = threadIdx.x; i < (int)gridDim.x; i += blockDim.x) {
            s1 += __ldcg(&g_p1[i]);
            s2 += __ldcg(&g_p2[i]);
        }
        #pragma unroll
        for (int o = 16; o > 0; o >>= 1) {
            s1 += __shfl_down_sync(0xffffffffu, s1, o);
            s2 += __shfl_down_sync(0xffffffffu, s2, o);
        }
        __syncthreads();
        if (lane == 0) { sh1[wid] = s1; sh2[wid] = s2; }
        __syncthreads();
        if (wid == 0) {
            double a = (lane < 4) ? sh1[lane] : 0.0;
            double c = (lane < 4) ? sh2[lane] : 0.0;
            #pragma unroll
            for (int o = 2; o > 0; o >>= 1) {
                a += __shfl_down_sync(0xffffffffu, a, o);
                c += __shfl_down_sync(0xffffffffu, c, o);
            }
            if (lane == 0) {
                double term_lik = -a / ((double)B * (double)(2 * MF));
                double term_q   =  c / (double)B;
                out[0] = (float)(term_lik + term_q + 1.3862943611198906); // + log(4)
                g_cnt = 0;
            }
        }
    }
}

extern "C" void kernel_launch(void* const* d_in, const int* in_sizes, int n_in,
                              void* d_out, int out_size)
{
    const float* x    = (const float*)d_in[0];
    const float* s    = (const float*)d_in[1];
    const float* ucat = (const float*)d_in[2];
    const float* utr  = (const float*)d_in[3];
    int B = in_sizes[0] / 105;

    int threads = 128;
    int blocks = (B + threads - 1) / threads;   // 1024 for B=131072
    bnn_all<<<blocks, threads>>>(x, s, ucat, utr, (float*)d_out, B);
}

// round 10
// speedup vs baseline: 1.1548x; 1.1548x over previous
#include <cuda_runtime.h>

#define NLAY 5
#define MIX  5
#define MF   50

typedef unsigned long long u64;

__device__ double g_p1[1024];
__device__ double g_p2[1024];
__device__ unsigned int g_cnt = 0;

// ---- f32x2 packed helpers ----
__device__ __forceinline__ u64 PK(float lo, float hi) {
    u64 r; asm("mov.b64 %0,{%1,%2};" : "=l"(r) : "f"(lo), "f"(hi)); return r;
}
__device__ __forceinline__ void UPK(u64 v, float& lo, float& hi) {
    asm("mov.b64 {%0,%1},%2;" : "=f"(lo), "=f"(hi) : "l"(v));
}
__device__ __forceinline__ u64 SP(float x) { return PK(x, x); }
__device__ __forceinline__ u64 F2(u64 a, u64 b, u64 c) {
    u64 r; asm("fma.rn.f32x2 %0,%1,%2,%3;" : "=l"(r) : "l"(a), "l"(b), "l"(c)); return r;
}
__device__ __forceinline__ u64 M2(u64 a, u64 b) {
    u64 r; asm("mul.rn.f32x2 %0,%1,%2;" : "=l"(r) : "l"(a), "l"(b)); return r;
}
__device__ __forceinline__ u64 A2(u64 a, u64 b) {
    u64 r; asm("add.rn.f32x2 %0,%1,%2;" : "=l"(r) : "l"(a), "l"(b)); return r;
}

__device__ __forceinline__ float ex2_(float v) {
    float r; asm("ex2.approx.f32 %0,%1;" : "=f"(r) : "f"(v)); return r;
}
__device__ __forceinline__ float sigmoidf_(float v) {
    return __fdividef(1.f, 1.f + __expf(-v));
}
__device__ __forceinline__ float softplusf_(float v) {
    return fmaxf(v, 0.f) + __logf(1.f + __expf(-fabsf(v)));
}
// Abramowitz-Stegun 26.2.17 normal CDF, |abs err| < 7.5e-8
__device__ __forceinline__ float ndtr_(float x) {
    float ax = fabsf(x);
    float t = __fdividef(1.f, fmaf(0.2316419f, ax, 1.f));
    float poly = t * fmaf(t, fmaf(t, fmaf(t, fmaf(t, 1.330274429f, -1.821255978f),
                         1.781477937f), -0.356563782f), 0.319381530f);
    float c = 0.39894228040f * __expf(-0.5f * ax * ax) * poly;
    return (x >= 0.f) ? 1.f - c : c;
}
// Giles erfinv-based inverse normal CDF
__device__ __forceinline__ float ndtri_(float p) {
    float x = fmaf(2.f, p, -1.f);
    x = fminf(fmaxf(x, -0.9999990f), 0.9999990f);
    float w = -__logf(fmaf(-x, x, 1.f));
    float z;
    if (w < 5.f) {
        w -= 2.5f;
        z =            2.81022636e-08f;
        z = fmaf(z, w, 3.43273939e-07f);
        z = fmaf(z, w, -3.5233877e-06f);
        z = fmaf(z, w, -4.39150654e-06f);
        z = fmaf(z, w, 0.00021858087f);
        z = fmaf(z, w, -0.00125372503f);
        z = fmaf(z, w, -0.00417768164f);
        z = fmaf(z, w, 0.246640727f);
        z = fmaf(z, w, 1.50140941f);
    } else {
        w = __fsqrt_rn(w) - 3.f;
        z =            -0.000200214257f;
        z = fmaf(z, w, 0.000100950558f);
        z = fmaf(z, w, 0.00134934322f);
        z = fmaf(z, w, -0.00367342844f);
        z = fmaf(z, w, 0.00573950773f);
        z = fmaf(z, w, -0.0076224613f);
        z = fmaf(z, w, 0.00943887047f);
        z = fmaf(z, w, 1.00167406f);
        z = fmaf(z, w, 2.83297682f);
    }
    return 1.41421356237f * z * x;
}

__global__ __launch_bounds__(128) void bnn_all(
    const float* __restrict__ x, const float* __restrict__ s,
    const float* __restrict__ ucat, const float* __restrict__ utr,
    float* __restrict__ out, int B)
{
    __shared__ float s_cf[MF];
    if (threadIdx.x < MF) {
        int i = threadIdx.x;
        s_cf[i]  = 1.9869176531e-4f * exp2f(0.16948612698f * (float)i);
    }
    __syncthreads();

    int b = blockIdx.x * blockDim.x + threadIdx.x;
    float ll_sum = 0.f;
    float lq = 0.f;
    if (b < B) {
        const float* sb = s + (size_t)b * 55;
        const float* xb = x + (size_t)b * 105;

        // ---- mixture weights ----
        float sq[MIX]; float sumsq = 0.f;
        #pragma unroll
        for (int m = 0; m < MIX; m++) { float v = sb[m*11 + 10]; sq[m] = v*v; sumsq += sq[m]; }
        float rinv = __fdividef(1.f, sumsq);

        // ---- categorical selection ----
        float u = ucat[b];
        float cum = 0.f; int cnt = 0;
        #pragma unroll
        for (int m = 0; m < MIX; m++) { cum += sq[m] * rinv; cnt += (u > cum) ? 1 : 0; }
        int comp = min(cnt, MIX - 1);

        // ---- truncated-normal sampling ----
        float q[NLAY];
        const float* sc = sb + comp * 11;
        #pragma unroll
        for (int l = 0; l < NLAY; l++) {
            float lc = 4.f * sigmoidf_(sc[l]);
            float sg = softplusf_(sc[5 + l]);
            float rs = __fdividef(1.f, sg);
            float aa = (0.1f - lc) * rs;
            float bb = (3.9f - lc) * rs;
            float Fa = ndtr_(aa);
            float Fb = ndtr_(bb);
            float p  = Fa + utr[(size_t)b * NLAY + l] * (Fb - Fa);
            p = fminf(fmaxf(p, 0.f), 1.f);
            float z = ndtri_(p);
            q[l] = fminf(fmaxf(fmaf(sg, z, lc), 0.1f), 3.9f);
        }

        // ---- physics precompute (normalized recursion constants) ----
        float sr[NLAY];
        #pragma unroll
        for (int l = 0; l < NLAY; l++) sr[l] = ex2_(q[l] * 1.66096404744368f);
        u64 tqP[NLAY - 1];
        #pragma unroll
        for (int j = 0; j < NLAY - 1; j++)
            tqP[j] = SP(2.f * xb[j] * __fdividef(1.f, sr[j]));
        // layer ratios (frequency-independent)
        float n3 = sr[4] * __fdividef(1.f, sr[3]);
        u64 rho3P = SP(sr[3] * __fdividef(1.f, sr[2]));
        u64 rho2P = SP(sr[2] * __fdividef(1.f, sr[1]));
        u64 rho1P = SP(sr[1] * __fdividef(1.f, sr[0]));
        u64 P0P   = SP(1.f + n3);
        u64 M0P   = SP(1.f - n3);
        u64 M0nP  = SP(n3 - 1.f);
        u64 Q0P   = SP(q[0]);

        // ---- packed constants ----
        const u64 C13  = SP(0.33333334f), Cm1_6 = SP(-0.16666667f);
        const u64 ONE2 = SP(1.0f), Cm1 = SP(-1.0f);
        const u64 A1  = SP(0.9999993329f),  A3  = SP(-0.3332985605f);
        const u64 A5  = SP(0.1994653599f),  A7  = SP(-0.1390853351f);
        const u64 A9  = SP(0.0964200441f),  A11 = SP(-0.0559098861f);
        const u64 A13 = SP(0.0218612288f),  A15 = SP(-0.0040540580f);
        const u64 C555 = SP(-555.555556f), CLN2 = SP(-0.69314718f);
        const u64 CC = SP(2.58761937f), CL102 = SP(0.30102999566f);
        const u64 PI4 = SP(0.78539816340f);

        u64 acc2 = 0ull;

        // ---- frequency loop: normalized (w-free) recursion, 2 freqs/iter ----
        // state (n, D); update: P=D+n, M=D-n, n'=rho*(P-eM), D'=P+eM
        // e^{-(1+i)t}: ejR = 1-t+t^3/3-t^4/6 (+t^5/30 err), tg = -ejC = t(1-t+t^2/3)
        #pragma unroll 1
        for (int p = 0; p < MF; p += 2) {
            u64 cf2 = PK(s_cf[p], s_cf[p + 1]);

            u64 nR, nC, DR, DC;
            {   // peeled layer j=3: D=1, n=n3 (both real)
                u64 tt = M2(cf2, tqP[3]);
                u64 t2 = M2(tt, tt);
                u64 c1 = F2(tt, Cm1_6, C13);
                u64 t3 = M2(tt, t2);
                u64 omt = F2(tt, Cm1, ONE2);
                u64 ejR = F2(c1, t3, omt);
                u64 g  = F2(t2, C13, omt);
                u64 tg = M2(tt, g);
                u64 eMR = M2(ejR, M0P);
                u64 eMC = M2(tg, M0nP);          // ejC*M0
                nR = M2(rho3P, F2(eMR, Cm1, P0P));
                nC = M2(rho3P, M2(tg, M0P));     // rho3*(-eMC)
                DR = A2(P0P, eMR);
                DC = eMC;
            }
            #pragma unroll
            for (int j = 2; j >= 0; j--) {
                u64 tt = M2(cf2, tqP[j]);
                u64 t2 = M2(tt, tt);
                u64 c1 = F2(tt, Cm1_6, C13);
                u64 t3 = M2(tt, t2);
                u64 omt = F2(tt, Cm1, ONE2);
                u64 ejR = F2(c1, t3, omt);
                u64 g  = F2(t2, C13, omt);
                u64 tg = M2(tt, g);              // = -ejC
                u64 PR = A2(DR, nR), PC = A2(DC, nC);
                u64 MR = F2(nR, Cm1, DR), MC = F2(nC, Cm1, DC);
                u64 eMR = F2(ejR, MR, M2(tg, MC));            // ejR*MR - ejC*MC
                u64 eMC = F2(ejR, MC, M2(M2(tg, MR), Cm1));   // ejR*MC + ejC*MR
                u64 uR = F2(eMR, Cm1, PR);
                u64 uC = F2(eMC, Cm1, PC);
                if (j == 2)      { nR = M2(rho2P, uR); nC = M2(rho2P, uC); }
                else if (j == 1) { nR = M2(rho1P, uR); nC = M2(rho1P, uC); }
                else             { nR = uR;            nC = uC;            }
                DR = A2(PR, eMR);
                DC = A2(PC, eMC);
            }
            // |u|^2, |D|^2, u*conj(D)
            u64 n2v = F2(nR, nR, M2(nC, nC));
            u64 d2v = F2(DR, DR, M2(DC, DC));
            u64 nrv = F2(nR, DR, M2(nC, DC));
            u64 ncv = F2(nC, DR, M2(M2(nR, DC), Cm1));
            float n2a, n2b, d2a, d2b, ra_, rb_, ca_, cb_;
            UPK(n2v, n2a, n2b); UPK(d2v, d2a, d2b);
            UPK(nrv, ra_, rb_); UPK(ncv, ca_, cb_);

            // aRes = q0 + 0.30103*(log2|u|^2 - log2|D|^2)
            u64 lgv = PK(__log2f(n2a) - __log2f(d2a), __log2f(n2b) - __log2f(d2b));
            u64 aResV = F2(CL102, lgv, Q0P);
            float aA, aB; UPK(aResV, aA, aB);

            // phase = pi/4 + atan(uc/ur), |uc/ur| < 1 guaranteed
            float r0 = __fdividef(ca_, ra_);
            float r1 = __fdividef(cb_, rb_);
            u64 rv = PK(r0, r1);
            u64 sv = M2(rv, rv);
            u64 pp = F2(sv, A15, A13); pp = F2(pp, sv, A11);
            pp = F2(pp, sv, A9);       pp = F2(pp, sv, A7);
            pp = F2(pp, sv, A5);       pp = F2(pp, sv, A3);
            pp = F2(pp, sv, A1);
            u64 phv = F2(pp, rv, PI4);
            float ph0, ph1; UPK(phv, ph0, ph1);

            float ra0 = __fdividef(aA - xb[NLAY + p],     aA);
            float ra1 = __fdividef(aB - xb[NLAY + p + 1], aB);
            u64 rAv = PK(ra0, ra1);
            u64 lgA = PK(__log2f(fabsf(aA)), __log2f(fabsf(aB)));
            acc2 = A2(acc2, F2(C555, M2(rAv, rAv), F2(CLN2, lgA, CC)));

            float rp0 = __fdividef(ph0 - xb[NLAY + MF + p],     ph0);
            float rp1 = __fdividef(ph1 - xb[NLAY + MF + p + 1], ph1);
            u64 rPv = PK(rp0, rp1);
            u64 lgP = PK(__log2f(ph0), __log2f(ph1));
            acc2 = A2(acc2, F2(C555, M2(rPv, rPv), F2(CLN2, lgP, CC)));
        }
        { float la, lb_; UPK(acc2, la, lb_); ll_sum = la + lb_; }

        // ---- term_q: fused-log form ----
        float clp[MIX];
        #pragma unroll
        for (int m = 0; m < MIX; m++) {
            const float* sm = sb + m * 11;
            float zacc = 0.f;
            float prod = 1.f;
            #pragma unroll
            for (int l = 0; l < NLAY; l++) {
                float lc = 4.f * sigmoidf_(sm[l]);
                float sg = softplusf_(sm[5 + l]);
                float rs = __fdividef(1.f, sg);
                float a_ = (0.f - lc) * rs;
                float b_ = (4.f - lc) * rs;
                float dF = ndtr_(b_) - ndtr_(a_);
                float zc = (q[l] - lc) * rs;
                zacc = fmaf(-0.5f, zc * zc, zacc);
                prod *= sg * dF;
            }
            clp[m] = zacc - 4.59469266f + __logf(__fdividef(sq[m] * rinv, prod));
        }
        float mx = clp[0];
        #pragma unroll
        for (int m = 1; m < MIX; m++) mx = fmaxf(mx, clp[m]);
        float se = 0.f;
        #pragma unroll
        for (int m = 0; m < MIX; m++) se += __expf(clp[m] - mx);
        lq = mx + __logf(se);
    }

    // ---- block reduction (double), 128 threads = 4 warps ----
    double v1 = (double)ll_sum, v2 = (double)lq;
    #pragma unroll
    for (int o = 16; o > 0; o >>= 1) {
        v1 += __shfl_down_sync(0xffffffffu, v1, o);
        v2 += __shfl_down_sync(0xffffffffu, v2, o);
    }
    __shared__ double sh1[4], sh2[4];
    __shared__ bool amLast;
    int lane = threadIdx.x & 31, wid = threadIdx.x >> 5;
    if (lane == 0) { sh1[wid] = v1; sh2[wid] = v2; }
    __syncthreads();
    if (wid == 0) {
        double a = (lane < 4) ? sh1[lane] : 0.0;
        double c = (lane < 4) ? sh2[lane] : 0.0;
        #pragma unroll
        for (int o = 2; o > 0; o >>= 1) {
            a += __shfl_down_sync(0xffffffffu, a, o);
            c += __shfl_down_sync(0xffffffffu, c, o);
        }
        if (lane == 0) {
            g_p1[blockIdx.x] = a;
            g_p2[blockIdx.x] = c;
            __threadfence();
            unsigned int t = atomicAdd(&g_cnt, 1u);
            amLast = (t == gridDim.x - 1);
        }
    }
    __syncthreads();

    if (amLast) {
        __threadfence();
        double s1 = 0.0, s2 = 0.0;
        for (int i = threadIdx.x; i < (int)gridDim.x; i += blockDim.x) {
            s1 += __ldcg(&g_p1[i]);
            s2 += __ldcg(&g_p2[i]);
        }
        #pragma unroll
        for (int o = 16; o > 0; o >>= 1) {
            s1 += __shfl_down_sync(0xffffffffu, s1, o);
            s2 += __shfl_down_sync(0xffffffffu, s2, o);
        }
        __syncthreads();
        if (lane == 0) { sh1[wid] = s1; sh2[wid] = s2; }
        __syncthreads();
        if (wid == 0) {
            double a = (lane < 4) ? sh1[lane] : 0.0;
            double c = (lane < 4) ? sh2[lane] : 0.0;
            #pragma unroll
            for (int o = 2; o > 0; o >>= 1) {
                a += __shfl_down_sync(0xffffffffu, a, o);
                c += __shfl_down_sync(0xffffffffu, c, o);
            }
            if (lane == 0) {
                double term_lik = -a / ((double)B * (double)(2 * MF));
                double term_q   =  c / (double)B;
                out[0] = (float)(term_lik + term_q + 1.3862943611198906); // + log(4)
                g_cnt = 0;
            }
        }
    }
}

extern "C" void kernel_launch(void* const* d_in, const int* in_sizes, int n_in,
                              void* d_out, int out_size)
{
    const float* x    = (const float*)d_in[0];
    const float* s    = (const float*)d_in[1];
    const float* ucat = (const float*)d_in[2];
    const float* utr  = (const float*)d_in[3];
    int B = in_sizes[0] / 105;

    int threads = 128;
    int blocks = (B + threads - 1) / threads;   // 1024 for B=131072
    bnn_all<<<blocks, threads>>>(x, s, ucat, utr, (float*)d_out, B);
}

// round 11
// speedup vs baseline: 1.2012x; 1.0402x over previous
#include <cuda_runtime.h>

#define NLAY 5
#define MIX  5
#define MF   50

typedef unsigned long long u64;

__device__ double g_p1[1024];
__device__ double g_p2[1024];
__device__ unsigned int g_cnt = 0;

// ---- f32x2 packed helpers ----
__device__ __forceinline__ u64 PK(float lo, float hi) {
    u64 r; asm("mov.b64 %0,{%1,%2};" : "=l"(r) : "f"(lo), "f"(hi)); return r;
}
__device__ __forceinline__ void UPK(u64 v, float& lo, float& hi) {
    asm("mov.b64 {%0,%1},%2;" : "=f"(lo), "=f"(hi) : "l"(v));
}
__device__ __forceinline__ u64 SP(float x) { return PK(x, x); }
__device__ __forceinline__ u64 F2(u64 a, u64 b, u64 c) {
    u64 r; asm("fma.rn.f32x2 %0,%1,%2,%3;" : "=l"(r) : "l"(a), "l"(b), "l"(c)); return r;
}
__device__ __forceinline__ u64 M2(u64 a, u64 b) {
    u64 r; asm("mul.rn.f32x2 %0,%1,%2;" : "=l"(r) : "l"(a), "l"(b)); return r;
}
__device__ __forceinline__ u64 A2(u64 a, u64 b) {
    u64 r; asm("add.rn.f32x2 %0,%1,%2;" : "=l"(r) : "l"(a), "l"(b)); return r;
}

__device__ __forceinline__ float ex2_(float v) {
    float r; asm("ex2.approx.f32 %0,%1;" : "=f"(r) : "f"(v)); return r;
}
__device__ __forceinline__ float sigmoidf_(float v) {
    return __fdividef(1.f, 1.f + __expf(-v));
}
__device__ __forceinline__ float softplusf_(float v) {
    return fmaxf(v, 0.f) + __logf(1.f + __expf(-fabsf(v)));
}
// Abramowitz-Stegun 26.2.17 normal CDF, |abs err| < 7.5e-8
__device__ __forceinline__ float ndtr_(float x) {
    float ax = fabsf(x);
    float t = __fdividef(1.f, fmaf(0.2316419f, ax, 1.f));
    float poly = t * fmaf(t, fmaf(t, fmaf(t, fmaf(t, 1.330274429f, -1.821255978f),
                         1.781477937f), -0.356563782f), 0.319381530f);
    float c = 0.39894228040f * __expf(-0.5f * ax * ax) * poly;
    return (x >= 0.f) ? 1.f - c : c;
}
// Giles erfinv-based inverse normal CDF
__device__ __forceinline__ float ndtri_(float p) {
    float x = fmaf(2.f, p, -1.f);
    x = fminf(fmaxf(x, -0.9999990f), 0.9999990f);
    float w = -__logf(fmaf(-x, x, 1.f));
    float z;
    if (w < 5.f) {
        w -= 2.5f;
        z =            2.81022636e-08f;
        z = fmaf(z, w, 3.43273939e-07f);
        z = fmaf(z, w, -3.5233877e-06f);
        z = fmaf(z, w, -4.39150654e-06f);
        z = fmaf(z, w, 0.00021858087f);
        z = fmaf(z, w, -0.00125372503f);
        z = fmaf(z, w, -0.00417768164f);
        z = fmaf(z, w, 0.246640727f);
        z = fmaf(z, w, 1.50140941f);
    } else {
        w = __fsqrt_rn(w) - 3.f;
        z =            -0.000200214257f;
        z = fmaf(z, w, 0.000100950558f);
        z = fmaf(z, w, 0.00134934322f);
        z = fmaf(z, w, -0.00367342844f);
        z = fmaf(z, w, 0.00573950773f);
        z = fmaf(z, w, -0.0076224613f);
        z = fmaf(z, w, 0.00943887047f);
        z = fmaf(z, w, 1.00167406f);
        z = fmaf(z, w, 2.83297682f);
    }
    return 1.41421356237f * z * x;
}

__global__ __launch_bounds__(128) void bnn_all(
    const float* __restrict__ x, const float* __restrict__ s,
    const float* __restrict__ ucat, const float* __restrict__ utr,
    float* __restrict__ out, int B)
{
    __shared__ u64 s_cfP[MF / 2];          // packed (cf[2i], cf[2i+1])
    if (threadIdx.x < MF / 2) {
        int i = threadIdx.x;
        float c0 = 1.9869176531e-4f * exp2f(0.16948612698f * (float)(2 * i));
        float c1 = 1.9869176531e-4f * exp2f(0.16948612698f * (float)(2 * i + 1));
        s_cfP[i] = PK(c0, c1);
    }
    __syncthreads();

    int b = blockIdx.x * blockDim.x + threadIdx.x;
    float ll_sum = 0.f;
    float lq = 0.f;
    if (b < B) {
        const float* sb = s + (size_t)b * 55;
        const float* xb = x + (size_t)b * 105;

        // ---- mixture weights ----
        float sq[MIX]; float sumsq = 0.f;
        #pragma unroll
        for (int m = 0; m < MIX; m++) { float v = sb[m*11 + 10]; sq[m] = v*v; sumsq += sq[m]; }
        float rinv = __fdividef(1.f, sumsq);

        // ---- categorical selection ----
        float u = ucat[b];
        float cum = 0.f; int cnt = 0;
        #pragma unroll
        for (int m = 0; m < MIX; m++) { cum += sq[m] * rinv; cnt += (u > cum) ? 1 : 0; }
        int comp = min(cnt, MIX - 1);

        // ---- truncated-normal sampling ----
        float q[NLAY];
        const float* sc = sb + comp * 11;
        #pragma unroll
        for (int l = 0; l < NLAY; l++) {
            float lc = 4.f * sigmoidf_(sc[l]);
            float sg = softplusf_(sc[5 + l]);
            float rs = __fdividef(1.f, sg);
            float aa = (0.1f - lc) * rs;
            float bb = (3.9f - lc) * rs;
            float Fa = ndtr_(aa);
            float Fb = ndtr_(bb);
            float p  = Fa + utr[(size_t)b * NLAY + l] * (Fb - Fa);
            p = fminf(fmaxf(p, 0.f), 1.f);
            float z = ndtri_(p);
            q[l] = fminf(fmaxf(fmaf(sg, z, lc), 0.1f), 3.9f);
        }

        // ---- physics precompute: (P,M)-space constants ----
        float sr[NLAY];
        #pragma unroll
        for (int l = 0; l < NLAY; l++) sr[l] = ex2_(q[l] * 1.66096404744368f);
        u64 tqP[NLAY - 1];
        #pragma unroll
        for (int j = 0; j < NLAY - 1; j++)
            tqP[j] = SP(2.f * xb[j] * __fdividef(1.f, sr[j]));
        float n3   = sr[4] * __fdividef(1.f, sr[3]);
        float rho3 = sr[3] * __fdividef(1.f, sr[2]);
        float rho2 = sr[2] * __fdividef(1.f, sr[1]);
        float rho1 = sr[1] * __fdividef(1.f, sr[0]);
        float k3 = (1.f - rho3) * __fdividef(1.f, 1.f + rho3);
        float k2 = (1.f - rho2) * __fdividef(1.f, 1.f + rho2);
        float k1 = (1.f - rho1) * __fdividef(1.f, 1.f + rho1);
        u64 KA2 = SP(k2), KA1 = SP(k1), KA3 = SP(k3);
        u64 P0P  = SP(1.f + n3);           // P0 (real)
        u64 M0P  = SP(1.f - n3);           // M0 (real)
        u64 M0nP = SP(n3 - 1.f);           // -M0
        u64 K3P0 = SP(k3 * (1.f + n3));    // kappa3 * P0
        u64 Q0P  = SP(q[0]);

        // ---- packed constants ----
        const u64 C13  = SP(0.33333334f), Cm1_6 = SP(-0.16666667f);
        const u64 ONE2 = SP(1.0f), Cm1 = SP(-1.0f);
        const u64 A1  = SP(0.9999993329f),  A3  = SP(-0.3332985605f);
        const u64 A5  = SP(0.1994653599f),  A7  = SP(-0.1390853351f);
        const u64 A9  = SP(0.0964200441f),  A11 = SP(-0.0559098861f);
        const u64 A13 = SP(0.0218612288f),  A15 = SP(-0.0040540580f);
        const u64 C555 = SP(-555.555556f), CLN2 = SP(-0.69314718f);
        const u64 CC = SP(2.58761937f), CL102 = SP(0.30102999566f);
        const u64 PI4 = SP(0.78539816340f);

        u64 acc2 = 0ull;

        // ---- frequency loop: (P,M)-space recursion, 2 freqs/iter ----
        // layer j (kappa_j): P' = P + k*eM, M' = k*P + eM   (scale 1/(1+rho) cancels)
        // top layer kappa=0: P'=P, M'=eM; then n = P-M, D = P+M (common scale cancels)
        #pragma unroll 1
        for (int ip = 0; ip < MF / 2; ip++) {
            int p = 2 * ip;
            u64 cf2 = s_cfP[ip];

            u64 PR, PC, MR, MC;
            {   // peeled bottom layer j=3 (real inputs P0, M0)
                u64 tt = M2(cf2, tqP[3]);
                u64 t2 = M2(tt, tt);
                u64 c1 = F2(tt, Cm1_6, C13);
                u64 t3 = M2(tt, t2);
                u64 omt = F2(tt, Cm1, ONE2);
                u64 ejR = F2(c1, t3, omt);
                u64 g  = F2(t2, C13, omt);
                u64 tg = M2(tt, g);                 // = -ejC
                u64 eMR = M2(ejR, M0P);
                u64 eMC = M2(tg, M0nP);             // ejC*M0
                PR = F2(KA3, eMR, P0P);
                PC = M2(KA3, eMC);
                MR = A2(K3P0, eMR);
                MC = eMC;
            }
            #pragma unroll
            for (int j = 2; j >= 1; j--) {
                u64 K = (j == 2) ? KA2 : KA1;
                u64 tt = M2(cf2, tqP[j]);
                u64 t2 = M2(tt, tt);
                u64 c1 = F2(tt, Cm1_6, C13);
                u64 t3 = M2(tt, t2);
                u64 omt = F2(tt, Cm1, ONE2);
                u64 ejR = F2(c1, t3, omt);
                u64 g  = F2(t2, C13, omt);
                u64 tg = M2(tt, g);
                u64 eMR = F2(ejR, MR, M2(tg, MC));            // ejR*MR - ejC*MC
                u64 eMC = F2(ejR, MC, M2(M2(tg, MR), Cm1));   // ejR*MC + ejC*MR
                u64 PRn = F2(K, eMR, PR);
                u64 PCn = F2(K, eMC, PC);
                MR = F2(K, PR, eMR);
                MC = F2(K, PC, eMC);
                PR = PRn; PC = PCn;
            }
            u64 nR, nC, DR, DC;
            {   // top layer j=0 (kappa=0): n = P - eM, D = P + eM
                u64 tt = M2(cf2, tqP[0]);
                u64 t2 = M2(tt, tt);
                u64 c1 = F2(tt, Cm1_6, C13);
                u64 t3 = M2(tt, t2);
                u64 omt = F2(tt, Cm1, ONE2);
                u64 ejR = F2(c1, t3, omt);
                u64 g  = F2(t2, C13, omt);
                u64 tg = M2(tt, g);
                u64 eMR = F2(ejR, MR, M2(tg, MC));
                u64 eMC = F2(ejR, MC, M2(M2(tg, MR), Cm1));
                nR = F2(eMR, Cm1, PR);
                nC = F2(eMC, Cm1, PC);
                DR = A2(PR, eMR);
                DC = A2(PC, eMC);
            }
            // |n|^2, |D|^2, n*conj(D)
            u64 n2v = F2(nR, nR, M2(nC, nC));
            u64 d2v = F2(DR, DR, M2(DC, DC));
            u64 nrv = F2(nR, DR, M2(nC, DC));
            u64 ncv = F2(nC, DR, M2(M2(nR, DC), Cm1));
            float n2a, n2b, d2a, d2b, ra_, rb_, ca_, cb_;
            UPK(n2v, n2a, n2b); UPK(d2v, d2a, d2b);
            UPK(nrv, ra_, rb_); UPK(ncv, ca_, cb_);

            // aRes = q0 + 0.30103*(log2|n|^2 - log2|D|^2)
            u64 lgv = PK(__log2f(n2a) - __log2f(d2a), __log2f(n2b) - __log2f(d2b));
            u64 aResV = F2(CL102, lgv, Q0P);
            float aA, aB; UPK(aResV, aA, aB);

            // phase = pi/4 + atan(nc/nr), |nc/nr| < 1 guaranteed
            float r0 = __fdividef(ca_, ra_);
            float r1 = __fdividef(cb_, rb_);
            u64 rv = PK(r0, r1);
            u64 sv = M2(rv, rv);
            u64 pp = F2(sv, A15, A13); pp = F2(pp, sv, A11);
            pp = F2(pp, sv, A9);       pp = F2(pp, sv, A7);
            pp = F2(pp, sv, A5);       pp = F2(pp, sv, A3);
            pp = F2(pp, sv, A1);
            u64 phv = F2(pp, rv, PI4);
            float ph0, ph1; UPK(phv, ph0, ph1);

            float ra0 = __fdividef(aA - xb[NLAY + p],     aA);
            float ra1 = __fdividef(aB - xb[NLAY + p + 1], aB);
            u64 rAv = PK(ra0, ra1);
            u64 lgA = PK(__log2f(fabsf(aA)), __log2f(fabsf(aB)));
            acc2 = A2(acc2, F2(C555, M2(rAv, rAv), F2(CLN2, lgA, CC)));

            float rp0 = __fdividef(ph0 - xb[NLAY + MF + p],     ph0);
            float rp1 = __fdividef(ph1 - xb[NLAY + MF + p + 1], ph1);
            u64 rPv = PK(rp0, rp1);
            u64 lgP = PK(__log2f(ph0), __log2f(ph1));
            acc2 = A2(acc2, F2(C555, M2(rPv, rPv), F2(CLN2, lgP, CC)));
        }
        { float la, lb_; UPK(acc2, la, lb_); ll_sum = la + lb_; }

        // ---- term_q: fused-log form ----
        float clp[MIX];
        #pragma unroll
        for (int m = 0; m < MIX; m++) {
            const float* sm = sb + m * 11;
            float zacc = 0.f;
            float prod = 1.f;
            #pragma unroll
            for (int l = 0; l < NLAY; l++) {
                float lc = 4.f * sigmoidf_(sm[l]);
                float sg = softplusf_(sm[5 + l]);
                float rs = __fdividef(1.f, sg);
                float a_ = (0.f - lc) * rs;
                float b_ = (4.f - lc) * rs;
                float dF = ndtr_(b_) - ndtr_(a_);
                float zc = (q[l] - lc) * rs;
                zacc = fmaf(-0.5f, zc * zc, zacc);
                prod *= sg * dF;
            }
            clp[m] = zacc - 4.59469266f + __logf(__fdividef(sq[m] * rinv, prod));
        }
        float mx = clp[0];
        #pragma unroll
        for (int m = 1; m < MIX; m++) mx = fmaxf(mx, clp[m]);
        float se = 0.f;
        #pragma unroll
        for (int m = 0; m < MIX; m++) se += __expf(clp[m] - mx);
        lq = mx + __logf(se);
    }

    // ---- block reduction (double), 128 threads = 4 warps ----
    double v1 = (double)ll_sum, v2 = (double)lq;
    #pragma unroll
    for (int o = 16; o > 0; o >>= 1) {
        v1 += __shfl_down_sync(0xffffffffu, v1, o);
        v2 += __shfl_down_sync(0xffffffffu, v2, o);
    }
    __shared__ double sh1[4], sh2[4];
    __shared__ bool amLast;
    int lane = threadIdx.x & 31, wid = threadIdx.x >> 5;
    if (lane == 0) { sh1[wid] = v1; sh2[wid] = v2; }
    __syncthreads();
    if (wid == 0) {
        double a = (lane < 4) ? sh1[lane] : 0.0;
        double c = (lane < 4) ? sh2[lane] : 0.0;
        #pragma unroll
        for (int o = 2; o > 0; o >>= 1) {
            a += __shfl_down_sync(0xffffffffu, a, o);
            c += __shfl_down_sync(0xffffffffu, c, o);
        }
        if (lane == 0) {
            g_p1[blockIdx.x] = a;
            g_p2[blockIdx.x] = c;
            __threadfence();
            unsigned int t = atomicAdd(&g_cnt, 1u);
            amLast = (t == gridDim.x - 1);
        }
    }
    __syncthreads();

    if (amLast) {
        __threadfence();
        double s1 = 0.0, s2 = 0.0;
        for (int i = threadIdx.x; i < (int)gridDim.x; i += blockDim.x) {
            s1 += __ldcg(&g_p1[i]);
            s2 += __ldcg(&g_p2[i]);
        }
        #pragma unroll
        for (int o = 16; o > 0; o >>= 1) {
            s1 += __shfl_down_sync(0xffffffffu, s1, o);
            s2 += __shfl_down_sync(0xffffffffu, s2, o);
        }
        __syncthreads();
        if (lane == 0) { sh1[wid] = s1; sh2[wid] = s2; }
        __syncthreads();
        if (wid == 0) {
            double a = (lane < 4) ? sh1[lane] : 0.0;
            double c = (lane < 4) ? sh2[lane] : 0.0;
            #pragma unroll
            for (int o = 2; o > 0; o >>= 1) {
                a += __shfl_down_sync(0xffffffffu, a, o);
                c += __shfl_down_sync(0xffffffffu, c, o);
            }
            if (lane == 0) {
                double term_lik = -a / ((double)B * (double)(2 * MF));
                double term_q   =  c / (double)B;
                out[0] = (float)(term_lik + term_q + 1.3862943611198906); // + log(4)
                g_cnt = 0;
            }
        }
    }
}

extern "C" void kernel_launch(void* const* d_in, const int* in_sizes, int n_in,
                              void* d_out, int out_size)
{
    const float* x    = (const float*)d_in[0];
    const float* s    = (const float*)d_in[1];
    const float* ucat = (const float*)d_in[2];
    const float* utr  = (const float*)d_in[3];
    int B = in_sizes[0] / 105;

    int threads = 128;
    int blocks = (B + threads - 1) / threads;   // 1024 for B=131072
    bnn_all<<<blocks, threads>>>(x, s, ucat, utr, (float*)d_out, B);
}